// round 12
// baseline (speedup 1.0000x reference)
#include <cuda_runtime.h>
#include <cstdint>
#include <cstddef>

#define D_MODEL 1024
#define NHEADS  16
#define DEPTH   64
#define BATCH   2
#define SEQ     2048
#define M_TOTAL (BATCH * SEQ)

__device__ float g_attn[(size_t)M_TOTAL * D_MODEL];
// pre-split bf16 hi/mid (2 per word), written by GEMM epilogues
__device__ uint32_t g_Qh[(size_t)M_TOTAL * 512];
__device__ uint32_t g_Qm[(size_t)M_TOTAL * 512];
__device__ uint32_t g_KVh[(size_t)M_TOTAL * 64];
__device__ uint32_t g_KVm[(size_t)M_TOTAL * 64];

// ---------------------------------------------------------------------------
// helpers (baseline sm_80-level PTX, legal on compute_103)
// ---------------------------------------------------------------------------
__device__ __forceinline__ uint32_t smem_u32(const void* p) {
    uint32_t a;
    asm("{ .reg .u64 t; cvta.to.shared.u64 t, %1; cvt.u32.u64 %0, t; }" : "=r"(a) : "l"(p));
    return a;
}
__device__ __forceinline__ uint32_t pack_bf16(float lo, float hi) {
    uint32_t r;
    asm("cvt.rn.bf16x2.f32 %0, %1, %2;" : "=r"(r) : "f"(hi), "f"(lo));
    return r;
}
__device__ __forceinline__ float trbf(float x) {
    return __uint_as_float(__float_as_uint(x) & 0xFFFF0000u);
}
__device__ __forceinline__ uint32_t trunc_pack(float a, float b) {
    return __byte_perm(__float_as_uint(a), __float_as_uint(b), 0x7632);
}
__device__ __forceinline__ void mma_bf16(float* c, const uint32_t* a, const uint32_t* b) {
    asm volatile("mma.sync.aligned.m16n8k16.row.col.f32.bf16.bf16.f32 "
        "{%0,%1,%2,%3}, {%4,%5,%6,%7}, {%8,%9}, {%0,%1,%2,%3};"
        : "+f"(c[0]), "+f"(c[1]), "+f"(c[2]), "+f"(c[3])
        : "r"(a[0]), "r"(a[1]), "r"(a[2]), "r"(a[3]), "r"(b[0]), "r"(b[1]));
}
#define LDSM_X4(r0, r1, r2, r3, addr) \
    asm volatile("ldmatrix.sync.aligned.m8n8.x4.shared.b16 {%0,%1,%2,%3}, [%4];" \
        : "=r"(r0), "=r"(r1), "=r"(r2), "=r"(r3) : "r"(addr))
#define LDSM_X4T(r0, r1, r2, r3, addr) \
    asm volatile("ldmatrix.sync.aligned.m8n8.x4.trans.shared.b16 {%0,%1,%2,%3}, [%4];" \
        : "=r"(r0), "=r"(r1), "=r"(r2), "=r"(r3) : "r"(addr))
#define CP_ASYNC16(dst, src) \
    asm volatile("cp.async.cg.shared.global [%0], [%1], 16;" :: "r"(dst), "l"(src))
#define CP_COMMIT() asm volatile("cp.async.commit_group;" ::: "memory")
#define CP_WAIT1()  asm volatile("cp.async.wait_group 1;" ::: "memory")
#define CP_WAIT0()  asm volatile("cp.async.wait_group 0;" ::: "memory")

// split one float4 into bf16 hi (truncate) + mid (rn residual), store 2+2 words
__device__ __forceinline__ void split_store(uint32_t* whi, uint32_t* wmid, int wi, float4 v) {
    uint32_t b0 = __float_as_uint(v.x), b1 = __float_as_uint(v.y);
    uint32_t b2 = __float_as_uint(v.z), b3 = __float_as_uint(v.w);
    *(uint2*)(whi + wi) = make_uint2(__byte_perm(b0, b1, 0x7632), __byte_perm(b2, b3, 0x7632));
    float m0 = v.x - __uint_as_float(b0 & 0xFFFF0000u);
    float m1 = v.y - __uint_as_float(b1 & 0xFFFF0000u);
    float m2 = v.z - __uint_as_float(b2 & 0xFFFF0000u);
    float m3 = v.w - __uint_as_float(b3 & 0xFFFF0000u);
    *(uint2*)(wmid + wi) = make_uint2(pack_bf16(m0, m1), pack_bf16(m2, m3));
}

// ===========================================================================
// Tensor-core GEMM bf16x3, 128x128 tile, BK=32, ldmatrix fragment loads.
// ===========================================================================
#define GSTRIDE 20

__global__ __launch_bounds__(256) void gemm_tc(
    const float* __restrict__ A, const float* __restrict__ W,
    const float* __restrict__ bias, float* __restrict__ C,
    uint32_t* __restrict__ dh, uint32_t* __restrict__ dm, float oscale,
    int M, int N, int K)
{
    __shared__ uint32_t Ahi[128 * GSTRIDE], Amid[128 * GSTRIDE];
    __shared__ uint32_t Bhi[128 * GSTRIDE], Bmid[128 * GSTRIDE];
    const int tid = threadIdx.x, wid = tid >> 5, lane = tid & 31;
    const int gid = lane >> 2, tig = lane & 3;
    const int warp_m = wid & 3, warp_n = wid >> 2;
    const int m0 = blockIdx.y * 128, n0 = blockIdx.x * 128;
    const int g = lane >> 3;

    // ldmatrix per-thread address components
    // A x4 (per array): m0 rows0-7 seg0 | m1 rows8-15 seg0 | m2 rows0-7 seg1 | m3 rows8-15 seg1
    const uint32_t a_off = (uint32_t)(((g & 1) * 8 + (lane & 7)) * 80 + (g >> 1) * 16);
    const uint32_t sAhi = smem_u32(Ahi) + (uint32_t)(warp_m * 32 * 80) + a_off;
    const uint32_t sAmid = smem_u32(Amid) + (uint32_t)(warp_m * 32 * 80) + a_off;
    // B x4 (hi/mid merged): m0 hi seg0 | m1 hi seg1 | m2 mid seg0 | m3 mid seg1
    const uint32_t b_base = ((g < 2) ? smem_u32(Bhi) : smem_u32(Bmid)) +
        (uint32_t)((warp_n * 64 + (lane & 7)) * 80 + (g & 1) * 16);

    float acc[2][8][4];
#pragma unroll
    for (int mt = 0; mt < 2; mt++)
#pragma unroll
        for (int nt = 0; nt < 8; nt++)
#pragma unroll
            for (int j = 0; j < 4; j++) acc[mt][nt][j] = 0.f;

    for (int k0 = 0; k0 < K; k0 += 32) {
        __syncthreads();
#pragma unroll
        for (int i = 0; i < 4; i++) {
            int e = tid + i * 256;
            int r = e >> 3, w8 = e & 7;
            float4 va = *(const float4*)(A + (size_t)(m0 + r) * K + k0 + w8 * 4);
            split_store(Ahi, Amid, r * GSTRIDE + w8 * 2, va);
            float4 vb = *(const float4*)(W + (size_t)(n0 + r) * K + k0 + w8 * 4);
            split_store(Bhi, Bmid, r * GSTRIDE + w8 * 2, vb);
        }
        __syncthreads();
#pragma unroll
        for (int ds = 0; ds < 2; ds++) {
            uint32_t ah[2][4], am[2][4];
#pragma unroll
            for (int mt = 0; mt < 2; mt++) {
                uint32_t ao = (uint32_t)(mt * 16 * 80 + ds * 32);
                LDSM_X4(ah[mt][0], ah[mt][1], ah[mt][2], ah[mt][3], sAhi + ao);
                LDSM_X4(am[mt][0], am[mt][1], am[mt][2], am[mt][3], sAmid + ao);
            }
#pragma unroll
            for (int nt = 0; nt < 8; nt++) {
                uint32_t bh[2], bm[2];
                LDSM_X4(bh[0], bh[1], bm[0], bm[1],
                        b_base + (uint32_t)(nt * 8 * 80 + ds * 32));
#pragma unroll
                for (int mt = 0; mt < 2; mt++) {
                    mma_bf16(acc[mt][nt], ah[mt], bh);
                    mma_bf16(acc[mt][nt], am[mt], bh);
                    mma_bf16(acc[mt][nt], ah[mt], bm);
                }
            }
        }
    }
#pragma unroll
    for (int mt = 0; mt < 2; mt++) {
        int row = m0 + warp_m * 32 + mt * 16 + gid;
#pragma unroll
        for (int nt = 0; nt < 8; nt++) {
            int col = n0 + warp_n * 64 + nt * 8 + tig * 2;
            float2 bv = *(const float2*)&bias[col];
            float v00 = acc[mt][nt][0] + bv.x, v01 = acc[mt][nt][1] + bv.y;
            float v10 = acc[mt][nt][2] + bv.x, v11 = acc[mt][nt][3] + bv.y;
            if (dh) {
                v00 *= oscale; v01 *= oscale; v10 *= oscale; v11 *= oscale;
                size_t w0 = (size_t)row * (N / 2) + col / 2;
                size_t w1 = w0 + (size_t)8 * (N / 2);
                dh[w0] = trunc_pack(v00, v01);
                dm[w0] = pack_bf16(v00 - trbf(v00), v01 - trbf(v01));
                dh[w1] = trunc_pack(v10, v11);
                dm[w1] = pack_bf16(v10 - trbf(v10), v11 - trbf(v11));
            } else {
                *(float2*)&C[(size_t)row * N + col] = make_float2(v00, v01);
                *(float2*)&C[(size_t)(row + 8) * N + col] = make_float2(v10, v11);
            }
        }
    }
}

// --------------- fp32 GEMM for KV (exact), split-output epilogue -----------
__global__ __launch_bounds__(256) void gemm_kv_split(
    const float* __restrict__ A, const float* __restrict__ W,
    const float* __restrict__ bias,
    uint32_t* __restrict__ dh, uint32_t* __restrict__ dm,
    int M, int N, int K)
{
    __shared__ float As[16][68];
    __shared__ float Ws[16][68];
    int tid = threadIdx.x;
    int m0 = blockIdx.y * 64, n0 = blockIdx.x * 64;
    int lr = tid >> 2, lq = tid & 3;
    int tx = tid & 15, ty = tid >> 4;
    float acc[4][4];
#pragma unroll
    for (int i = 0; i < 4; i++)
#pragma unroll
        for (int j = 0; j < 4; j++) acc[i][j] = 0.f;
    const float* Aptr = A + (size_t)(m0 + lr) * K + lq * 4;
    const float* Wptr = W + (size_t)(n0 + lr) * K + lq * 4;
    for (int k0 = 0; k0 < K; k0 += 16) {
        float4 av = *(const float4*)(Aptr + k0);
        float4 wv = *(const float4*)(Wptr + k0);
        __syncthreads();
        As[lq*4+0][lr] = av.x; As[lq*4+1][lr] = av.y; As[lq*4+2][lr] = av.z; As[lq*4+3][lr] = av.w;
        Ws[lq*4+0][lr] = wv.x; Ws[lq*4+1][lr] = wv.y; Ws[lq*4+2][lr] = wv.z; Ws[lq*4+3][lr] = wv.w;
        __syncthreads();
#pragma unroll
        for (int kk = 0; kk < 16; kk++) {
            float4 a = *(const float4*)&As[kk][ty * 4];
            float4 w = *(const float4*)&Ws[kk][tx * 4];
            acc[0][0] += a.x*w.x; acc[0][1] += a.x*w.y; acc[0][2] += a.x*w.z; acc[0][3] += a.x*w.w;
            acc[1][0] += a.y*w.x; acc[1][1] += a.y*w.y; acc[1][2] += a.y*w.z; acc[1][3] += a.y*w.w;
            acc[2][0] += a.z*w.x; acc[2][1] += a.z*w.y; acc[2][2] += a.z*w.z; acc[2][3] += a.z*w.w;
            acc[3][0] += a.w*w.x; acc[3][1] += a.w*w.y; acc[3][2] += a.w*w.z; acc[3][3] += a.w*w.w;
        }
    }
    float4 bv = *(const float4*)&bias[n0 + tx * 4];
#pragma unroll
    for (int i = 0; i < 4; i++) {
        float o0 = acc[i][0] + bv.x, o1 = acc[i][1] + bv.y;
        float o2 = acc[i][2] + bv.z, o3 = acc[i][3] + bv.w;
        size_t w = (size_t)(m0 + ty * 4 + i) * (N / 2) + (n0 + tx * 4) / 2;
        *(uint2*)&dh[w] = make_uint2(trunc_pack(o0, o1), trunc_pack(o2, o3));
        *(uint2*)&dm[w] = make_uint2(pack_bf16(o0 - trbf(o0), o1 - trbf(o1)),
                                     pack_bf16(o2 - trbf(o2), o3 - trbf(o3)));
    }
}

// ---------------------------------------------------------------------------
// Flash attention, TQ=128, 256 threads (8 warps; warp owns 16 q rows).
// ---------------------------------------------------------------------------
#define KSTR 36                       // words per K/V smem row (144 B)
#define STG  (128 * KSTR * 4)         // 18432 B per stage array
#define OFF_K0HI  0
#define OFF_K0MID (1 * STG)
#define OFF_K1HI  (2 * STG)
#define OFF_K1MID (3 * STG)
#define OFF_V0HI  (4 * STG)
#define OFF_V0MID (5 * STG)
#define OFF_V1HI  (6 * STG)
#define OFF_V1MID (7 * STG)
#define OFF_QHI   (8 * STG)
#define OFF_QMID  (9 * STG)
#define ATTN_SMEM (10 * STG)          // 184320 B

__device__ __forceinline__ void prefetch_kv(
    const uint32_t* __restrict__ KVh, const uint32_t* __restrict__ KVm,
    int rowbase, int voff, uint32_t dhi, uint32_t dmid, int tid)
{
#pragma unroll
    for (int i = 0; i < 8; i++) {
        int e = tid + i * 256;
        int r = e >> 4, t = e & 15, w8 = t & 7;
        const uint32_t* src = ((t & 8) ? KVm : KVh) + (size_t)(rowbase + r) * 64 + voff + w8 * 4;
        uint32_t dst = ((t & 8) ? dmid : dhi) + (uint32_t)(r * 144 + w8 * 16);
        CP_ASYNC16(dst, src);
    }
}

// 16 q rows x 128 keys; K frags via hi/mid-merged ldmatrix.x4
#define QK_CHUNK(kb, c) do { \
    _Pragma("unroll") for (int _j = 0; _j < 16; _j++) { \
        (c)[_j][0] = 0.f; (c)[_j][1] = 0.f; (c)[_j][2] = 0.f; (c)[_j][3] = 0.f; } \
    _Pragma("unroll") for (int _ds = 0; _ds < 4; _ds++) { \
        _Pragma("unroll") for (int _j = 0; _j < 16; _j++) { \
            uint32_t _bh[2], _bm[2]; \
            LDSM_X4(_bh[0], _bh[1], _bm[0], _bm[1], \
                    (kb) + (uint32_t)(_j * 1152 + _ds * 32)); \
            mma_bf16((c)[_j], qh[_ds], _bh); \
            mma_bf16((c)[_j], qm[_ds], _bh); \
            mma_bf16((c)[_j], qh[_ds], _bm); \
        } } } while (0)

__global__ __launch_bounds__(256, 1) void attn_flash(
    const uint32_t* __restrict__ Qh, const uint32_t* __restrict__ Qm,
    const uint32_t* __restrict__ KVh, const uint32_t* __restrict__ KVm,
    float* __restrict__ Wout, float* __restrict__ Aout)
{
    extern __shared__ char sm[];
    const int tid = threadIdx.x, wid = tid >> 5, lane = tid & 31;
    const int gid = lane >> 2, tig = lane & 3;
    const int b = blockIdx.z, h = blockIdx.y, q0 = blockIdx.x * 128;
    const uint32_t sb = smem_u32(sm);
    const int rb = b * SEQ;

    uint32_t* qw_hi  = (uint32_t*)(sm + OFF_QHI);
    uint32_t* qw_mid = (uint32_t*)(sm + OFF_QMID);

    // ldmatrix per-thread address components
    // QK K-frag x4: m0 hi seg0 | m1 hi seg1 | m2 mid seg0 | m3 mid seg1
    const uint32_t kq_off = (uint32_t)((lane & 7) * 144 + ((lane >> 3) & 1) * 16)
                          + ((lane >= 16) ? (uint32_t)STG : 0u);
    // PV V-frag x4 trans: m0 hi rows0-7 | m1 hi rows8-15 | m2 mid rows0-7 | m3 mid rows8-15
    const uint32_t vq_off = (uint32_t)((lane & 15) * 144)
                          + ((lane >= 16) ? (uint32_t)STG : 0u);

    prefetch_kv(KVh, KVm, rb, 0, sb + OFF_K0HI, sb + OFF_K0MID, tid);
    CP_COMMIT();

    // stage Q rows q0..q0+127
#pragma unroll
    for (int i = 0; i < 4; i++) {
        int e = tid + i * 256;
        int r = e >> 3, cw = (e & 7) * 4;
        size_t g = (size_t)(rb + q0 + r) * 512 + h * 32 + cw;
        *(uint4*)&qw_hi[r * KSTR + cw]  = *(const uint4*)&Qh[g];
        *(uint4*)&qw_mid[r * KSTR + cw] = *(const uint4*)&Qm[g];
    }
    __syncthreads();

    uint32_t qh[4][4], qm[4][4];
#pragma unroll
    for (int ds = 0; ds < 4; ds++) {
        int w0 = (wid * 16 + gid) * KSTR + ds * 8 + tig, w1 = w0 + 8 * KSTR;
        qh[ds][0] = qw_hi[w0];  qh[ds][1] = qw_hi[w1];
        qh[ds][2] = qw_hi[w0 + 4]; qh[ds][3] = qw_hi[w1 + 4];
        qm[ds][0] = qw_mid[w0]; qm[ds][1] = qw_mid[w1];
        qm[ds][2] = qw_mid[w0 + 4]; qm[ds][3] = qw_mid[w1 + 4];
    }

    float m0 = -1e30f, s0 = 0.f, m1 = -1e30f, s1 = 0.f;
    float c[16][4];

    // ---- Pass A: online row max & expsum ----
    for (int ch = 0; ch < 16; ch++) {
        if (ch < 15) {
            int alt = (ch + 1) & 1;
            prefetch_kv(KVh, KVm, rb + (ch + 1) * 128, 0,
                        sb + (alt ? OFF_K1HI : OFF_K0HI),
                        sb + (alt ? OFF_K1MID : OFF_K0MID), tid);
        }
        CP_COMMIT(); CP_WAIT1(); __syncthreads();
        const uint32_t kb = sb + ((ch & 1) ? OFF_K1HI : OFF_K0HI) + kq_off;
        QK_CHUNK(kb, c);
        float mx0 = -1e30f, mx1 = -1e30f;
#pragma unroll
        for (int j = 0; j < 16; j++) {
            mx0 = fmaxf(mx0, fmaxf(c[j][0], c[j][1]));
            mx1 = fmaxf(mx1, fmaxf(c[j][2], c[j][3]));
        }
        mx0 = fmaxf(mx0, __shfl_xor_sync(0xffffffffu, mx0, 1));
        mx0 = fmaxf(mx0, __shfl_xor_sync(0xffffffffu, mx0, 2));
        mx1 = fmaxf(mx1, __shfl_xor_sync(0xffffffffu, mx1, 1));
        mx1 = fmaxf(mx1, __shfl_xor_sync(0xffffffffu, mx1, 2));
        float nm0 = fmaxf(m0, mx0), nm1 = fmaxf(m1, mx1);
        float a0 = 0.f, a1 = 0.f;
#pragma unroll
        for (int j = 0; j < 16; j++) {
            a0 += __expf(c[j][0] - nm0) + __expf(c[j][1] - nm0);
            a1 += __expf(c[j][2] - nm1) + __expf(c[j][3] - nm1);
        }
        a0 += __shfl_xor_sync(0xffffffffu, a0, 1);
        a0 += __shfl_xor_sync(0xffffffffu, a0, 2);
        a1 += __shfl_xor_sync(0xffffffffu, a1, 1);
        a1 += __shfl_xor_sync(0xffffffffu, a1, 2);
        s0 = s0 * __expf(m0 - nm0) + a0; m0 = nm0;
        s1 = s1 * __expf(m1 - nm1) + a1; m1 = nm1;
        __syncthreads();
    }
    CP_WAIT0();
    const float inv0 = 1.f / s0, inv1 = 1.f / s1;
    __syncthreads();

    // ---- Pass B: weights + PV ----
    prefetch_kv(KVh, KVm, rb, 0,  sb + OFF_K0HI, sb + OFF_K0MID, tid);
    prefetch_kv(KVh, KVm, rb, 32, sb + OFF_V0HI, sb + OFF_V0MID, tid);
    CP_COMMIT();

    float pv[8][4];
#pragma unroll
    for (int n = 0; n < 8; n++) { pv[n][0] = pv[n][1] = pv[n][2] = pv[n][3] = 0.f; }

    float* wrow0 = Wout + ((size_t)(b * NHEADS + h) * SEQ + (q0 + wid * 16 + gid)) * SEQ;
    float* wrow1 = wrow0 + (size_t)8 * SEQ;

    for (int ch = 0; ch < 16; ch++) {
        if (ch < 15) {
            int alt = (ch + 1) & 1;
            prefetch_kv(KVh, KVm, rb + (ch + 1) * 128, 0,
                        sb + (alt ? OFF_K1HI : OFF_K0HI),
                        sb + (alt ? OFF_K1MID : OFF_K0MID), tid);
            prefetch_kv(KVh, KVm, rb + (ch + 1) * 128, 32,
                        sb + (alt ? OFF_V1HI : OFF_V0HI),
                        sb + (alt ? OFF_V1MID : OFF_V0MID), tid);
        }
        CP_COMMIT(); CP_WAIT1(); __syncthreads();
        int cur = ch & 1;
        const uint32_t kb = sb + (cur ? OFF_K1HI : OFF_K0HI) + kq_off;
        const uint32_t vb = sb + (cur ? OFF_V1HI : OFF_V0HI) + vq_off;

        QK_CHUNK(kb, c);

#pragma unroll
        for (int j = 0; j < 16; j++) {
            float p0 = __expf(c[j][0] - m0) * inv0;
            float p1 = __expf(c[j][1] - m0) * inv0;
            float p2 = __expf(c[j][2] - m1) * inv1;
            float p3 = __expf(c[j][3] - m1) * inv1;
            *(float2*)&wrow0[ch * 128 + j * 8 + tig * 2] = make_float2(p0, p1);
            *(float2*)&wrow1[ch * 128 + j * 8 + tig * 2] = make_float2(p2, p3);
            c[j][0] = p0; c[j][1] = p1; c[j][2] = p2; c[j][3] = p3;
        }

#pragma unroll
        for (int s = 0; s < 8; s++) {
            uint32_t ah[4], am[4];
            float e00 = c[2*s][0],   e01 = c[2*s][1],   e02 = c[2*s][2],   e03 = c[2*s][3];
            float e10 = c[2*s+1][0], e11 = c[2*s+1][1], e12 = c[2*s+1][2], e13 = c[2*s+1][3];
            ah[0] = trunc_pack(e00, e01); ah[1] = trunc_pack(e02, e03);
            ah[2] = trunc_pack(e10, e11); ah[3] = trunc_pack(e12, e13);
            am[0] = pack_bf16(e00 - trbf(e00), e01 - trbf(e01));
            am[1] = pack_bf16(e02 - trbf(e02), e03 - trbf(e03));
            am[2] = pack_bf16(e10 - trbf(e10), e11 - trbf(e11));
            am[3] = pack_bf16(e12 - trbf(e12), e13 - trbf(e13));
#pragma unroll
            for (int n = 0; n < 8; n++) {
                uint32_t bh[2], bm[2];
                LDSM_X4T(bh[0], bh[1], bm[0], bm[1],
                         vb + (uint32_t)(s * 2304 + n * 16));
                mma_bf16(pv[n], ah, bh);
                mma_bf16(pv[n], am, bh);
                mma_bf16(pv[n], ah, bm);
            }
        }
        __syncthreads();
    }

    int row0 = rb + q0 + wid * 16 + gid;
#pragma unroll
    for (int n = 0; n < 8; n++) {
        int dcol = h * DEPTH + n * 8 + tig * 2;
        *(float2*)&Aout[(size_t)row0 * D_MODEL + dcol]       = make_float2(pv[n][0], pv[n][1]);
        *(float2*)&Aout[(size_t)(row0 + 8) * D_MODEL + dcol] = make_float2(pv[n][2], pv[n][3]);
    }
}

// ---------------------------------------------------------------------------
extern "C" void kernel_launch(void* const* d_in, const int* in_sizes, int n_in,
                              void* d_out, int out_size)
{
    const float* Q       = (const float*)d_in[0];
    const float* K       = (const float*)d_in[1];
    // d_in[2] = V (unused: reference derives V from the KV projection)
    const float* WQ_w    = (const float*)d_in[3];
    const float* WQ_b    = (const float*)d_in[4];
    const float* WKV_w   = (const float*)d_in[5];
    const float* WKV_b   = (const float*)d_in[6];
    const float* dense_w = (const float*)d_in[7];
    const float* dense_b = (const float*)d_in[8];

    float* out     = (float*)d_out;
    float* weights = out + (size_t)M_TOTAL * D_MODEL;

    float* attn;
    uint32_t *qhp, *qmp, *kvh, *kvm;
    cudaGetSymbolAddress((void**)&attn, g_attn);
    cudaGetSymbolAddress((void**)&qhp,  g_Qh);
    cudaGetSymbolAddress((void**)&qmp,  g_Qm);
    cudaGetSymbolAddress((void**)&kvh,  g_KVh);
    cudaGetSymbolAddress((void**)&kvm,  g_KVm);

    cudaFuncSetAttribute(attn_flash, cudaFuncAttributeMaxDynamicSharedMemorySize, ATTN_SMEM);

    // 1) Qp-split = 0.125*(Q @ WQ_w^T + b)  -> g_Qh/g_Qm
    gemm_tc<<<dim3(D_MODEL / 128, M_TOTAL / 128), 256>>>(
        Q, WQ_w, WQ_b, nullptr, qhp, qmp, 0.125f, M_TOTAL, D_MODEL, D_MODEL);
    // 2) KV-split = K @ WKV_w^T + b (exact fp32 compute) -> g_KVh/g_KVm
    gemm_kv_split<<<dim3((2 * DEPTH) / 64, M_TOTAL / 64), 256>>>(
        K, WKV_w, WKV_b, kvh, kvm, M_TOTAL, 2 * DEPTH, D_MODEL);
    // 3) flash attention: weights + context
    attn_flash<<<dim3(SEQ / 128, NHEADS, BATCH), 256, ATTN_SMEM>>>(
        qhp, qmp, kvh, kvm, weights, attn);
    // 4) out = attn @ dense_w^T + b (fp32 output)
    gemm_tc<<<dim3(D_MODEL / 128, M_TOTAL / 128), 256>>>(
        attn, dense_w, dense_b, out, nullptr, nullptr, 1.f, M_TOTAL, D_MODEL, D_MODEL);
}

// round 14
// speedup vs baseline: 1.1638x; 1.1638x over previous
#include <cuda_runtime.h>
#include <cstdint>
#include <cstddef>

#define D_MODEL 1024
#define NHEADS  16
#define DEPTH   64
#define BATCH   2
#define SEQ     2048
#define M_TOTAL (BATCH * SEQ)

__device__ float g_attn[(size_t)M_TOTAL * D_MODEL];
// pre-split bf16 hi/mid (2 per word), written by GEMM epilogues
__device__ uint32_t g_Qh[(size_t)M_TOTAL * 512];
__device__ uint32_t g_Qm[(size_t)M_TOTAL * 512];
__device__ uint32_t g_KVh[(size_t)M_TOTAL * 64];
__device__ uint32_t g_KVm[(size_t)M_TOTAL * 64];

// ---------------------------------------------------------------------------
// helpers (baseline sm_80-level PTX, legal on compute_103)
// ---------------------------------------------------------------------------
__device__ __forceinline__ uint32_t smem_u32(const void* p) {
    uint32_t a;
    asm("{ .reg .u64 t; cvta.to.shared.u64 t, %1; cvt.u32.u64 %0, t; }" : "=r"(a) : "l"(p));
    return a;
}
__device__ __forceinline__ uint32_t pack_bf16(float lo, float hi) {
    uint32_t r;
    asm("cvt.rn.bf16x2.f32 %0, %1, %2;" : "=r"(r) : "f"(hi), "f"(lo));
    return r;
}
__device__ __forceinline__ float trbf(float x) {
    return __uint_as_float(__float_as_uint(x) & 0xFFFF0000u);
}
__device__ __forceinline__ uint32_t trunc_pack(float a, float b) {
    return __byte_perm(__float_as_uint(a), __float_as_uint(b), 0x7632);
}
__device__ __forceinline__ void mma_bf16(float* c, const uint32_t* a, const uint32_t* b) {
    asm volatile("mma.sync.aligned.m16n8k16.row.col.f32.bf16.bf16.f32 "
        "{%0,%1,%2,%3}, {%4,%5,%6,%7}, {%8,%9}, {%0,%1,%2,%3};"
        : "+f"(c[0]), "+f"(c[1]), "+f"(c[2]), "+f"(c[3])
        : "r"(a[0]), "r"(a[1]), "r"(a[2]), "r"(a[3]), "r"(b[0]), "r"(b[1]));
}
#define LDSM_X2T(r0, r1, addr) \
    asm volatile("ldmatrix.sync.aligned.m8n8.x2.trans.shared.b16 {%0,%1}, [%2];" \
        : "=r"(r0), "=r"(r1) : "r"(addr))
#define CP_ASYNC16(dst, src) \
    asm volatile("cp.async.cg.shared.global [%0], [%1], 16;" :: "r"(dst), "l"(src))
#define CP_COMMIT() asm volatile("cp.async.commit_group;" ::: "memory")
#define CP_WAIT1()  asm volatile("cp.async.wait_group 1;" ::: "memory")
#define CP_WAIT0()  asm volatile("cp.async.wait_group 0;" ::: "memory")

// split one float4 into bf16 hi (truncate) + mid (rn residual), store 2+2 words
__device__ __forceinline__ void split_store(uint32_t* whi, uint32_t* wmid, int wi, float4 v) {
    uint32_t b0 = __float_as_uint(v.x), b1 = __float_as_uint(v.y);
    uint32_t b2 = __float_as_uint(v.z), b3 = __float_as_uint(v.w);
    *(uint2*)(whi + wi) = make_uint2(__byte_perm(b0, b1, 0x7632), __byte_perm(b2, b3, 0x7632));
    float m0 = v.x - __uint_as_float(b0 & 0xFFFF0000u);
    float m1 = v.y - __uint_as_float(b1 & 0xFFFF0000u);
    float m2 = v.z - __uint_as_float(b2 & 0xFFFF0000u);
    float m3 = v.w - __uint_as_float(b3 & 0xFFFF0000u);
    *(uint2*)(wmid + wi) = make_uint2(pack_bf16(m0, m1), pack_bf16(m2, m3));
}

// ===========================================================================
// Tensor-core GEMM bf16x3, 128x128 tile, BK=32 (R11 version; 128 regs,
// 2 CTAs/SM pinned via launch bounds).
// ===========================================================================
#define GSTRIDE 20

__global__ __launch_bounds__(256, 2) void gemm_tc(
    const float* __restrict__ A, const float* __restrict__ W,
    const float* __restrict__ bias, float* __restrict__ C,
    uint32_t* __restrict__ dh, uint32_t* __restrict__ dm, float oscale,
    int M, int N, int K)
{
    __shared__ uint32_t Ahi[128 * GSTRIDE], Amid[128 * GSTRIDE];
    __shared__ uint32_t Bhi[128 * GSTRIDE], Bmid[128 * GSTRIDE];
    const int tid = threadIdx.x, wid = tid >> 5, lane = tid & 31;
    const int gid = lane >> 2, tig = lane & 3;
    const int warp_m = wid & 3, warp_n = wid >> 2;
    const int m0 = blockIdx.y * 128, n0 = blockIdx.x * 128;

    float acc[2][8][4];
#pragma unroll
    for (int mt = 0; mt < 2; mt++)
#pragma unroll
        for (int nt = 0; nt < 8; nt++)
#pragma unroll
            for (int j = 0; j < 4; j++) acc[mt][nt][j] = 0.f;

    for (int k0 = 0; k0 < K; k0 += 32) {
        __syncthreads();
#pragma unroll
        for (int i = 0; i < 4; i++) {
            int e = tid + i * 256;
            int r = e >> 3, w8 = e & 7;
            float4 va = *(const float4*)(A + (size_t)(m0 + r) * K + k0 + w8 * 4);
            split_store(Ahi, Amid, r * GSTRIDE + w8 * 2, va);
            float4 vb = *(const float4*)(W + (size_t)(n0 + r) * K + k0 + w8 * 4);
            split_store(Bhi, Bmid, r * GSTRIDE + w8 * 2, vb);
        }
        __syncthreads();
#pragma unroll
        for (int ds = 0; ds < 2; ds++) {
            uint32_t ah[2][4], am[2][4];
#pragma unroll
            for (int mt = 0; mt < 2; mt++) {
                int r0 = (warp_m * 32 + mt * 16 + gid) * GSTRIDE + ds * 8 + tig;
                int r1 = r0 + 8 * GSTRIDE;
                ah[mt][0] = Ahi[r0];     ah[mt][1] = Ahi[r1];
                ah[mt][2] = Ahi[r0 + 4]; ah[mt][3] = Ahi[r1 + 4];
                am[mt][0] = Amid[r0];     am[mt][1] = Amid[r1];
                am[mt][2] = Amid[r0 + 4]; am[mt][3] = Amid[r1 + 4];
            }
#pragma unroll
            for (int nt = 0; nt < 8; nt++) {
                int wi = (warp_n * 64 + nt * 8 + gid) * GSTRIDE + ds * 8 + tig;
                uint32_t bh[2] = { Bhi[wi], Bhi[wi + 4] };
                uint32_t bm[2] = { Bmid[wi], Bmid[wi + 4] };
#pragma unroll
                for (int mt = 0; mt < 2; mt++) {
                    mma_bf16(acc[mt][nt], ah[mt], bh);
                    mma_bf16(acc[mt][nt], am[mt], bh);
                    mma_bf16(acc[mt][nt], ah[mt], bm);
                }
            }
        }
    }
#pragma unroll
    for (int mt = 0; mt < 2; mt++) {
        int row = m0 + warp_m * 32 + mt * 16 + gid;
#pragma unroll
        for (int nt = 0; nt < 8; nt++) {
            int col = n0 + warp_n * 64 + nt * 8 + tig * 2;
            float2 bv = *(const float2*)&bias[col];
            float v00 = acc[mt][nt][0] + bv.x, v01 = acc[mt][nt][1] + bv.y;
            float v10 = acc[mt][nt][2] + bv.x, v11 = acc[mt][nt][3] + bv.y;
            if (dh) {
                v00 *= oscale; v01 *= oscale; v10 *= oscale; v11 *= oscale;
                size_t w0 = (size_t)row * (N / 2) + col / 2;
                size_t w1 = w0 + (size_t)8 * (N / 2);
                dh[w0] = trunc_pack(v00, v01);
                dm[w0] = pack_bf16(v00 - trbf(v00), v01 - trbf(v01));
                dh[w1] = trunc_pack(v10, v11);
                dm[w1] = pack_bf16(v10 - trbf(v10), v11 - trbf(v11));
            } else {
                *(float2*)&C[(size_t)row * N + col] = make_float2(v00, v01);
                *(float2*)&C[(size_t)(row + 8) * N + col] = make_float2(v10, v11);
            }
        }
    }
}

// --------------- fp32 GEMM for KV (exact), split-output epilogue -----------
__global__ __launch_bounds__(256) void gemm_kv_split(
    const float* __restrict__ A, const float* __restrict__ W,
    const float* __restrict__ bias,
    uint32_t* __restrict__ dh, uint32_t* __restrict__ dm,
    int M, int N, int K)
{
    __shared__ float As[16][68];
    __shared__ float Ws[16][68];
    int tid = threadIdx.x;
    int m0 = blockIdx.y * 64, n0 = blockIdx.x * 64;
    int lr = tid >> 2, lq = tid & 3;
    int tx = tid & 15, ty = tid >> 4;
    float acc[4][4];
#pragma unroll
    for (int i = 0; i < 4; i++)
#pragma unroll
        for (int j = 0; j < 4; j++) acc[i][j] = 0.f;
    const float* Aptr = A + (size_t)(m0 + lr) * K + lq * 4;
    const float* Wptr = W + (size_t)(n0 + lr) * K + lq * 4;
    for (int k0 = 0; k0 < K; k0 += 16) {
        float4 av = *(const float4*)(Aptr + k0);
        float4 wv = *(const float4*)(Wptr + k0);
        __syncthreads();
        As[lq*4+0][lr] = av.x; As[lq*4+1][lr] = av.y; As[lq*4+2][lr] = av.z; As[lq*4+3][lr] = av.w;
        Ws[lq*4+0][lr] = wv.x; Ws[lq*4+1][lr] = wv.y; Ws[lq*4+2][lr] = wv.z; Ws[lq*4+3][lr] = wv.w;
        __syncthreads();
#pragma unroll
        for (int kk = 0; kk < 16; kk++) {
            float4 a = *(const float4*)&As[kk][ty * 4];
            float4 w = *(const float4*)&Ws[kk][tx * 4];
            acc[0][0] += a.x*w.x; acc[0][1] += a.x*w.y; acc[0][2] += a.x*w.z; acc[0][3] += a.x*w.w;
            acc[1][0] += a.y*w.x; acc[1][1] += a.y*w.y; acc[1][2] += a.y*w.z; acc[1][3] += a.y*w.w;
            acc[2][0] += a.z*w.x; acc[2][1] += a.z*w.y; acc[2][2] += a.z*w.z; acc[2][3] += a.z*w.w;
            acc[3][0] += a.w*w.x; acc[3][1] += a.w*w.y; acc[3][2] += a.w*w.z; acc[3][3] += a.w*w.w;
        }
    }
    float4 bv = *(const float4*)&bias[n0 + tx * 4];
#pragma unroll
    for (int i = 0; i < 4; i++) {
        float o0 = acc[i][0] + bv.x, o1 = acc[i][1] + bv.y;
        float o2 = acc[i][2] + bv.z, o3 = acc[i][3] + bv.w;
        size_t w = (size_t)(m0 + ty * 4 + i) * (N / 2) + (n0 + tx * 4) / 2;
        *(uint2*)&dh[w] = make_uint2(trunc_pack(o0, o1), trunc_pack(o2, o3));
        *(uint2*)&dm[w] = make_uint2(pack_bf16(o0 - trbf(o0), o1 - trbf(o1)),
                                     pack_bf16(o2 - trbf(o2), o3 - trbf(o3)));
    }
}

// ---------------------------------------------------------------------------
// Flash attention, TQ=128, 256 threads, 110.6 KB smem -> 2 CTAs/SM.
// Pass A: K double-buffered (V buffers reused as alternate K stage),
//         QK in j-blocks of 4 (c[4][4]) with online (m,s).
// Pass B: K+V single-buffered; per-16-key slice: QK (c[2][4]) -> exp ->
//         weights write -> PV. Register-lean to fit 128 regs.
// ---------------------------------------------------------------------------
#define KSTR 36                       // words per K/V smem row (144 B)
#define STG  (128 * KSTR * 4)         // 18432 B per stage array
#define OFF_KHI  0
#define OFF_KMID (1 * STG)
#define OFF_VHI  (2 * STG)
#define OFF_VMID (3 * STG)
#define OFF_QHI  (4 * STG)
#define OFF_QMID (5 * STG)
#define ATTN_SMEM (6 * STG)           // 110592 B

__device__ __forceinline__ void prefetch_kv(
    const uint32_t* __restrict__ KVh, const uint32_t* __restrict__ KVm,
    int rowbase, int voff, uint32_t dhi, uint32_t dmid, int tid)
{
#pragma unroll
    for (int i = 0; i < 8; i++) {
        int e = tid + i * 256;
        int r = e >> 4, t = e & 15, w8 = t & 7;
        const uint32_t* src = ((t & 8) ? KVm : KVh) + (size_t)(rowbase + r) * 64 + voff + w8 * 4;
        uint32_t dst = ((t & 8) ? dmid : dhi) + (uint32_t)(r * 144 + w8 * 16);
        CP_ASYNC16(dst, src);
    }
}

__global__ __launch_bounds__(256, 2) void attn_flash(
    const uint32_t* __restrict__ Qh, const uint32_t* __restrict__ Qm,
    const uint32_t* __restrict__ KVh, const uint32_t* __restrict__ KVm,
    float* __restrict__ Wout, float* __restrict__ Aout)
{
    extern __shared__ char sm[];
    const int tid = threadIdx.x, wid = tid >> 5, lane = tid & 31;
    const int gid = lane >> 2, tig = lane & 3;
    const int b = blockIdx.z, h = blockIdx.y, q0 = blockIdx.x * 128;
    const uint32_t sb = smem_u32(sm);
    const int rb = b * SEQ;

    uint32_t* qw_hi  = (uint32_t*)(sm + OFF_QHI);
    uint32_t* qw_mid = (uint32_t*)(sm + OFF_QMID);

    prefetch_kv(KVh, KVm, rb, 0, sb + OFF_KHI, sb + OFF_KMID, tid);
    CP_COMMIT();

    // stage Q rows q0..q0+127
#pragma unroll
    for (int i = 0; i < 4; i++) {
        int e = tid + i * 256;
        int r = e >> 3, cw = (e & 7) * 4;
        size_t g = (size_t)(rb + q0 + r) * 512 + h * 32 + cw;
        *(uint4*)&qw_hi[r * KSTR + cw]  = *(const uint4*)&Qh[g];
        *(uint4*)&qw_mid[r * KSTR + cw] = *(const uint4*)&Qm[g];
    }
    __syncthreads();

    uint32_t qh[4][4], qm[4][4];
#pragma unroll
    for (int ds = 0; ds < 4; ds++) {
        int w0 = (wid * 16 + gid) * KSTR + ds * 8 + tig, w1 = w0 + 8 * KSTR;
        qh[ds][0] = qw_hi[w0];  qh[ds][1] = qw_hi[w1];
        qh[ds][2] = qw_hi[w0 + 4]; qh[ds][3] = qw_hi[w1 + 4];
        qm[ds][0] = qw_mid[w0]; qm[ds][1] = qw_mid[w1];
        qm[ds][2] = qw_mid[w0 + 4]; qm[ds][3] = qw_mid[w1 + 4];
    }

    float m0 = -1e30f, s0 = 0.f, m1 = -1e30f, s1 = 0.f;

    // ---- Pass A: online row max & expsum (K double-buffered via V bufs) ----
    for (int ch = 0; ch < 16; ch++) {
        if (ch < 15) {
            int alt = (ch + 1) & 1;
            prefetch_kv(KVh, KVm, rb + (ch + 1) * 128, 0,
                        sb + (alt ? OFF_VHI : OFF_KHI),
                        sb + (alt ? OFF_VMID : OFF_KMID), tid);
        }
        CP_COMMIT(); CP_WAIT1(); __syncthreads();
        const uint32_t* khi  = (const uint32_t*)(sm + ((ch & 1) ? OFF_VHI : OFF_KHI));
        const uint32_t* kmid = (const uint32_t*)(sm + ((ch & 1) ? OFF_VMID : OFF_KMID));
#pragma unroll
        for (int blk = 0; blk < 4; blk++) {
            float c4[4][4];
#pragma unroll
            for (int j4 = 0; j4 < 4; j4++) {
                c4[j4][0] = 0.f; c4[j4][1] = 0.f; c4[j4][2] = 0.f; c4[j4][3] = 0.f;
            }
#pragma unroll
            for (int ds = 0; ds < 4; ds++) {
#pragma unroll
                for (int j4 = 0; j4 < 4; j4++) {
                    int wi = ((blk * 4 + j4) * 8 + gid) * KSTR + ds * 8 + tig;
                    uint32_t bh[2] = { khi[wi],  khi[wi + 4]  };
                    uint32_t bm[2] = { kmid[wi], kmid[wi + 4] };
                    mma_bf16(c4[j4], qh[ds], bh);
                    mma_bf16(c4[j4], qm[ds], bh);
                    mma_bf16(c4[j4], qh[ds], bm);
                }
            }
            float mx0 = -1e30f, mx1 = -1e30f;
#pragma unroll
            for (int j4 = 0; j4 < 4; j4++) {
                mx0 = fmaxf(mx0, fmaxf(c4[j4][0], c4[j4][1]));
                mx1 = fmaxf(mx1, fmaxf(c4[j4][2], c4[j4][3]));
            }
            mx0 = fmaxf(mx0, __shfl_xor_sync(0xffffffffu, mx0, 1));
            mx0 = fmaxf(mx0, __shfl_xor_sync(0xffffffffu, mx0, 2));
            mx1 = fmaxf(mx1, __shfl_xor_sync(0xffffffffu, mx1, 1));
            mx1 = fmaxf(mx1, __shfl_xor_sync(0xffffffffu, mx1, 2));
            float nm0 = fmaxf(m0, mx0), nm1 = fmaxf(m1, mx1);
            float a0 = 0.f, a1 = 0.f;
#pragma unroll
            for (int j4 = 0; j4 < 4; j4++) {
                a0 += __expf(c4[j4][0] - nm0) + __expf(c4[j4][1] - nm0);
                a1 += __expf(c4[j4][2] - nm1) + __expf(c4[j4][3] - nm1);
            }
            a0 += __shfl_xor_sync(0xffffffffu, a0, 1);
            a0 += __shfl_xor_sync(0xffffffffu, a0, 2);
            a1 += __shfl_xor_sync(0xffffffffu, a1, 1);
            a1 += __shfl_xor_sync(0xffffffffu, a1, 2);
            s0 = s0 * __expf(m0 - nm0) + a0; m0 = nm0;
            s1 = s1 * __expf(m1 - nm1) + a1; m1 = nm1;
        }
        __syncthreads();
    }
    CP_WAIT0();
    const float inv0 = 1.f / s0, inv1 = 1.f / s1;
    __syncthreads();

    // ---- Pass B: weights + PV (K+V single-buffered) ----
    prefetch_kv(KVh, KVm, rb, 0,  sb + OFF_KHI, sb + OFF_KMID, tid);
    prefetch_kv(KVh, KVm, rb, 32, sb + OFF_VHI, sb + OFF_VMID, tid);
    CP_COMMIT();

    float pv[8][4];
#pragma unroll
    for (int n = 0; n < 8; n++) { pv[n][0] = pv[n][1] = pv[n][2] = pv[n][3] = 0.f; }

    float* wrow0 = Wout + ((size_t)(b * NHEADS + h) * SEQ + (q0 + wid * 16 + gid)) * SEQ;
    float* wrow1 = wrow0 + (size_t)8 * SEQ;

    const uint32_t* khi  = (const uint32_t*)(sm + OFF_KHI);
    const uint32_t* kmid = (const uint32_t*)(sm + OFF_KMID);

    for (int ch = 0; ch < 16; ch++) {
        CP_WAIT0(); __syncthreads();
#pragma unroll
        for (int s = 0; s < 8; s++) {
            float c2[2][4];
            c2[0][0] = c2[0][1] = c2[0][2] = c2[0][3] = 0.f;
            c2[1][0] = c2[1][1] = c2[1][2] = c2[1][3] = 0.f;
#pragma unroll
            for (int ds = 0; ds < 4; ds++) {
#pragma unroll
                for (int jj = 0; jj < 2; jj++) {
                    int wi = ((2 * s + jj) * 8 + gid) * KSTR + ds * 8 + tig;
                    uint32_t bh[2] = { khi[wi],  khi[wi + 4]  };
                    uint32_t bm[2] = { kmid[wi], kmid[wi + 4] };
                    mma_bf16(c2[jj], qh[ds], bh);
                    mma_bf16(c2[jj], qm[ds], bh);
                    mma_bf16(c2[jj], qh[ds], bm);
                }
            }
#pragma unroll
            for (int jj = 0; jj < 2; jj++) {
                float p0 = __expf(c2[jj][0] - m0) * inv0;
                float p1 = __expf(c2[jj][1] - m0) * inv0;
                float p2 = __expf(c2[jj][2] - m1) * inv1;
                float p3 = __expf(c2[jj][3] - m1) * inv1;
                int col = ch * 128 + (2 * s + jj) * 8 + tig * 2;
                *(float2*)&wrow0[col] = make_float2(p0, p1);
                *(float2*)&wrow1[col] = make_float2(p2, p3);
                c2[jj][0] = p0; c2[jj][1] = p1; c2[jj][2] = p2; c2[jj][3] = p3;
            }
            uint32_t ah[4], am[4];
            ah[0] = trunc_pack(c2[0][0], c2[0][1]); ah[1] = trunc_pack(c2[0][2], c2[0][3]);
            ah[2] = trunc_pack(c2[1][0], c2[1][1]); ah[3] = trunc_pack(c2[1][2], c2[1][3]);
            am[0] = pack_bf16(c2[0][0] - trbf(c2[0][0]), c2[0][1] - trbf(c2[0][1]));
            am[1] = pack_bf16(c2[0][2] - trbf(c2[0][2]), c2[0][3] - trbf(c2[0][3]));
            am[2] = pack_bf16(c2[1][0] - trbf(c2[1][0]), c2[1][1] - trbf(c2[1][1]));
            am[3] = pack_bf16(c2[1][2] - trbf(c2[1][2]), c2[1][3] - trbf(c2[1][3]));
            uint32_t vrow = (uint32_t)((s * 16 + (lane & 15)) * 144);
#pragma unroll
            for (int n = 0; n < 8; n++) {
                uint32_t bh[2], bm[2];
                LDSM_X2T(bh[0], bh[1], sb + OFF_VHI + vrow + n * 16);
                LDSM_X2T(bm[0], bm[1], sb + OFF_VMID + vrow + n * 16);
                mma_bf16(pv[n], ah, bh);
                mma_bf16(pv[n], am, bh);
                mma_bf16(pv[n], ah, bm);
            }
        }
        __syncthreads();
        if (ch < 15) {
            prefetch_kv(KVh, KVm, rb + (ch + 1) * 128, 0,  sb + OFF_KHI, sb + OFF_KMID, tid);
            prefetch_kv(KVh, KVm, rb + (ch + 1) * 128, 32, sb + OFF_VHI, sb + OFF_VMID, tid);
            CP_COMMIT();
        }
    }

    int row0 = rb + q0 + wid * 16 + gid;
#pragma unroll
    for (int n = 0; n < 8; n++) {
        int dcol = h * DEPTH + n * 8 + tig * 2;
        *(float2*)&Aout[(size_t)row0 * D_MODEL + dcol]       = make_float2(pv[n][0], pv[n][1]);
        *(float2*)&Aout[(size_t)(row0 + 8) * D_MODEL + dcol] = make_float2(pv[n][2], pv[n][3]);
    }
}

// ---------------------------------------------------------------------------
extern "C" void kernel_launch(void* const* d_in, const int* in_sizes, int n_in,
                              void* d_out, int out_size)
{
    const float* Q       = (const float*)d_in[0];
    const float* K       = (const float*)d_in[1];
    // d_in[2] = V (unused: reference derives V from the KV projection)
    const float* WQ_w    = (const float*)d_in[3];
    const float* WQ_b    = (const float*)d_in[4];
    const float* WKV_w   = (const float*)d_in[5];
    const float* WKV_b   = (const float*)d_in[6];
    const float* dense_w = (const float*)d_in[7];
    const float* dense_b = (const float*)d_in[8];

    float* out     = (float*)d_out;
    float* weights = out + (size_t)M_TOTAL * D_MODEL;

    float* attn;
    uint32_t *qhp, *qmp, *kvh, *kvm;
    cudaGetSymbolAddress((void**)&attn, g_attn);
    cudaGetSymbolAddress((void**)&qhp,  g_Qh);
    cudaGetSymbolAddress((void**)&qmp,  g_Qm);
    cudaGetSymbolAddress((void**)&kvh,  g_KVh);
    cudaGetSymbolAddress((void**)&kvm,  g_KVm);

    cudaFuncSetAttribute(attn_flash, cudaFuncAttributeMaxDynamicSharedMemorySize, ATTN_SMEM);

    // 1) Qp-split = 0.125*(Q @ WQ_w^T + b)  -> g_Qh/g_Qm
    gemm_tc<<<dim3(D_MODEL / 128, M_TOTAL / 128), 256>>>(
        Q, WQ_w, WQ_b, nullptr, qhp, qmp, 0.125f, M_TOTAL, D_MODEL, D_MODEL);
    // 2) KV-split = K @ WKV_w^T + b (exact fp32 compute) -> g_KVh/g_KVm
    gemm_kv_split<<<dim3((2 * DEPTH) / 64, M_TOTAL / 64), 256>>>(
        K, WKV_w, WKV_b, kvh, kvm, M_TOTAL, 2 * DEPTH, D_MODEL);
    // 3) flash attention: weights + context
    attn_flash<<<dim3(SEQ / 128, NHEADS, BATCH), 256, ATTN_SMEM>>>(
        qhp, qmp, kvh, kvm, weights, attn);
    // 4) out = attn @ dense_w^T + b (fp32 output)
    gemm_tc<<<dim3(D_MODEL / 128, M_TOTAL / 128), 256>>>(
        attn, dense_w, dense_b, out, nullptr, nullptr, 1.f, M_TOTAL, D_MODEL, D_MODEL);
}

// round 17
// speedup vs baseline: 1.3308x; 1.1435x over previous
#include <cuda_runtime.h>
#include <cstdint>
#include <cstddef>

#define D_MODEL 1024
#define NHEADS  16
#define DEPTH   64
#define BATCH   2
#define SEQ     2048
#define M_TOTAL (BATCH * SEQ)

__device__ float g_attn[(size_t)M_TOTAL * D_MODEL];
// pre-split bf16 hi(trunc)/mid(rn residual) + rn (round-nearest) variants
__device__ uint32_t g_Qh[(size_t)M_TOTAL * 512];
__device__ uint32_t g_Qm[(size_t)M_TOTAL * 512];
__device__ uint32_t g_Qr[(size_t)M_TOTAL * 512];
__device__ uint32_t g_KVh[(size_t)M_TOTAL * 64];
__device__ uint32_t g_KVm[(size_t)M_TOTAL * 64];
__device__ uint32_t g_KVr[(size_t)M_TOTAL * 64];

// ---------------------------------------------------------------------------
// helpers (baseline sm_80-level PTX, legal on compute_103)
// ---------------------------------------------------------------------------
__device__ __forceinline__ uint32_t smem_u32(const void* p) {
    uint32_t a;
    asm("{ .reg .u64 t; cvta.to.shared.u64 t, %1; cvt.u32.u64 %0, t; }" : "=r"(a) : "l"(p));
    return a;
}
__device__ __forceinline__ uint32_t pack_bf16(float lo, float hi) {
    uint32_t r;
    asm("cvt.rn.bf16x2.f32 %0, %1, %2;" : "=r"(r) : "f"(hi), "f"(lo));
    return r;
}
__device__ __forceinline__ float trbf(float x) {
    return __uint_as_float(__float_as_uint(x) & 0xFFFF0000u);
}
__device__ __forceinline__ uint32_t trunc_pack(float a, float b) {
    return __byte_perm(__float_as_uint(a), __float_as_uint(b), 0x7632);
}
__device__ __forceinline__ void mma_bf16(float* c, const uint32_t* a, const uint32_t* b) {
    asm volatile("mma.sync.aligned.m16n8k16.row.col.f32.bf16.bf16.f32 "
        "{%0,%1,%2,%3}, {%4,%5,%6,%7}, {%8,%9}, {%0,%1,%2,%3};"
        : "+f"(c[0]), "+f"(c[1]), "+f"(c[2]), "+f"(c[3])
        : "r"(a[0]), "r"(a[1]), "r"(a[2]), "r"(a[3]), "r"(b[0]), "r"(b[1]));
}
#define LDSM_X2T(r0, r1, addr) \
    asm volatile("ldmatrix.sync.aligned.m8n8.x2.trans.shared.b16 {%0,%1}, [%2];" \
        : "=r"(r0), "=r"(r1) : "r"(addr))
#define CP_ASYNC16(dst, src) \
    asm volatile("cp.async.cg.shared.global [%0], [%1], 16;" :: "r"(dst), "l"(src))
#define CP_COMMIT() asm volatile("cp.async.commit_group;" ::: "memory")
#define CP_WAIT1()  asm volatile("cp.async.wait_group 1;" ::: "memory")
#define CP_WAIT0()  asm volatile("cp.async.wait_group 0;" ::: "memory")

// split one float4 into bf16 hi (truncate) + mid (rn residual), store 2+2 words
__device__ __forceinline__ void split_store(uint32_t* whi, uint32_t* wmid, int wi, float4 v) {
    uint32_t b0 = __float_as_uint(v.x), b1 = __float_as_uint(v.y);
    uint32_t b2 = __float_as_uint(v.z), b3 = __float_as_uint(v.w);
    *(uint2*)(whi + wi) = make_uint2(__byte_perm(b0, b1, 0x7632), __byte_perm(b2, b3, 0x7632));
    float m0 = v.x - __uint_as_float(b0 & 0xFFFF0000u);
    float m1 = v.y - __uint_as_float(b1 & 0xFFFF0000u);
    float m2 = v.z - __uint_as_float(b2 & 0xFFFF0000u);
    float m3 = v.w - __uint_as_float(b3 & 0xFFFF0000u);
    *(uint2*)(wmid + wi) = make_uint2(pack_bf16(m0, m1), pack_bf16(m2, m3));
}

// ===========================================================================
// Tensor-core GEMM bf16x3, 128x128 tile, BK=32 (2 CTAs/SM pinned).
// Split epilogue also writes an rn-bf16 copy (dr) for the attention pass A.
// ===========================================================================
#define GSTRIDE 20

__global__ __launch_bounds__(256, 2) void gemm_tc(
    const float* __restrict__ A, const float* __restrict__ W,
    const float* __restrict__ bias, float* __restrict__ C,
    uint32_t* __restrict__ dh, uint32_t* __restrict__ dm,
    uint32_t* __restrict__ dr, float oscale,
    int M, int N, int K)
{
    __shared__ uint32_t Ahi[128 * GSTRIDE], Amid[128 * GSTRIDE];
    __shared__ uint32_t Bhi[128 * GSTRIDE], Bmid[128 * GSTRIDE];
    const int tid = threadIdx.x, wid = tid >> 5, lane = tid & 31;
    const int gid = lane >> 2, tig = lane & 3;
    const int warp_m = wid & 3, warp_n = wid >> 2;
    const int m0 = blockIdx.y * 128, n0 = blockIdx.x * 128;

    float acc[2][8][4];
#pragma unroll
    for (int mt = 0; mt < 2; mt++)
#pragma unroll
        for (int nt = 0; nt < 8; nt++)
#pragma unroll
            for (int j = 0; j < 4; j++) acc[mt][nt][j] = 0.f;

    for (int k0 = 0; k0 < K; k0 += 32) {
        __syncthreads();
#pragma unroll
        for (int i = 0; i < 4; i++) {
            int e = tid + i * 256;
            int r = e >> 3, w8 = e & 7;
            float4 va = *(const float4*)(A + (size_t)(m0 + r) * K + k0 + w8 * 4);
            split_store(Ahi, Amid, r * GSTRIDE + w8 * 2, va);
            float4 vb = *(const float4*)(W + (size_t)(n0 + r) * K + k0 + w8 * 4);
            split_store(Bhi, Bmid, r * GSTRIDE + w8 * 2, vb);
        }
        __syncthreads();
#pragma unroll
        for (int ds = 0; ds < 2; ds++) {
            uint32_t ah[2][4], am[2][4];
#pragma unroll
            for (int mt = 0; mt < 2; mt++) {
                int r0 = (warp_m * 32 + mt * 16 + gid) * GSTRIDE + ds * 8 + tig;
                int r1 = r0 + 8 * GSTRIDE;
                ah[mt][0] = Ahi[r0];     ah[mt][1] = Ahi[r1];
                ah[mt][2] = Ahi[r0 + 4]; ah[mt][3] = Ahi[r1 + 4];
                am[mt][0] = Amid[r0];     am[mt][1] = Amid[r1];
                am[mt][2] = Amid[r0 + 4]; am[mt][3] = Amid[r1 + 4];
            }
#pragma unroll
            for (int nt = 0; nt < 8; nt++) {
                int wi = (warp_n * 64 + nt * 8 + gid) * GSTRIDE + ds * 8 + tig;
                uint32_t bh[2] = { Bhi[wi], Bhi[wi + 4] };
                uint32_t bm[2] = { Bmid[wi], Bmid[wi + 4] };
#pragma unroll
                for (int mt = 0; mt < 2; mt++) {
                    mma_bf16(acc[mt][nt], ah[mt], bh);
                    mma_bf16(acc[mt][nt], am[mt], bh);
                    mma_bf16(acc[mt][nt], ah[mt], bm);
                }
            }
        }
    }
#pragma unroll
    for (int mt = 0; mt < 2; mt++) {
        int row = m0 + warp_m * 32 + mt * 16 + gid;
#pragma unroll
        for (int nt = 0; nt < 8; nt++) {
            int col = n0 + warp_n * 64 + nt * 8 + tig * 2;
            float2 bv = *(const float2*)&bias[col];
            float v00 = acc[mt][nt][0] + bv.x, v01 = acc[mt][nt][1] + bv.y;
            float v10 = acc[mt][nt][2] + bv.x, v11 = acc[mt][nt][3] + bv.y;
            if (dh) {
                v00 *= oscale; v01 *= oscale; v10 *= oscale; v11 *= oscale;
                size_t w0 = (size_t)row * (N / 2) + col / 2;
                size_t w1 = w0 + (size_t)8 * (N / 2);
                dh[w0] = trunc_pack(v00, v01);
                dm[w0] = pack_bf16(v00 - trbf(v00), v01 - trbf(v01));
                dr[w0] = pack_bf16(v00, v01);
                dh[w1] = trunc_pack(v10, v11);
                dm[w1] = pack_bf16(v10 - trbf(v10), v11 - trbf(v11));
                dr[w1] = pack_bf16(v10, v11);
            } else {
                *(float2*)&C[(size_t)row * N + col] = make_float2(v00, v01);
                *(float2*)&C[(size_t)(row + 8) * N + col] = make_float2(v10, v11);
            }
        }
    }
}

// --------------- fp32 GEMM for KV (exact), split-output epilogue -----------
__global__ __launch_bounds__(256) void gemm_kv_split(
    const float* __restrict__ A, const float* __restrict__ W,
    const float* __restrict__ bias,
    uint32_t* __restrict__ dh, uint32_t* __restrict__ dm,
    uint32_t* __restrict__ dr,
    int M, int N, int K)
{
    __shared__ float As[16][68];
    __shared__ float Ws[16][68];
    int tid = threadIdx.x;
    int m0 = blockIdx.y * 64, n0 = blockIdx.x * 64;
    int lr = tid >> 2, lq = tid & 3;
    int tx = tid & 15, ty = tid >> 4;
    float acc[4][4];
#pragma unroll
    for (int i = 0; i < 4; i++)
#pragma unroll
        for (int j = 0; j < 4; j++) acc[i][j] = 0.f;
    const float* Aptr = A + (size_t)(m0 + lr) * K + lq * 4;
    const float* Wptr = W + (size_t)(n0 + lr) * K + lq * 4;
    for (int k0 = 0; k0 < K; k0 += 16) {
        float4 av = *(const float4*)(Aptr + k0);
        float4 wv = *(const float4*)(Wptr + k0);
        __syncthreads();
        As[lq*4+0][lr] = av.x; As[lq*4+1][lr] = av.y; As[lq*4+2][lr] = av.z; As[lq*4+3][lr] = av.w;
        Ws[lq*4+0][lr] = wv.x; Ws[lq*4+1][lr] = wv.y; Ws[lq*4+2][lr] = wv.z; Ws[lq*4+3][lr] = wv.w;
        __syncthreads();
#pragma unroll
        for (int kk = 0; kk < 16; kk++) {
            float4 a = *(const float4*)&As[kk][ty * 4];
            float4 w = *(const float4*)&Ws[kk][tx * 4];
            acc[0][0] += a.x*w.x; acc[0][1] += a.x*w.y; acc[0][2] += a.x*w.z; acc[0][3] += a.x*w.w;
            acc[1][0] += a.y*w.x; acc[1][1] += a.y*w.y; acc[1][2] += a.y*w.z; acc[1][3] += a.y*w.w;
            acc[2][0] += a.z*w.x; acc[2][1] += a.z*w.y; acc[2][2] += a.z*w.z; acc[2][3] += a.z*w.w;
            acc[3][0] += a.w*w.x; acc[3][1] += a.w*w.y; acc[3][2] += a.w*w.z; acc[3][3] += a.w*w.w;
        }
    }
    float4 bv = *(const float4*)&bias[n0 + tx * 4];
#pragma unroll
    for (int i = 0; i < 4; i++) {
        float o0 = acc[i][0] + bv.x, o1 = acc[i][1] + bv.y;
        float o2 = acc[i][2] + bv.z, o3 = acc[i][3] + bv.w;
        size_t w = (size_t)(m0 + ty * 4 + i) * (N / 2) + (n0 + tx * 4) / 2;
        *(uint2*)&dh[w] = make_uint2(trunc_pack(o0, o1), trunc_pack(o2, o3));
        *(uint2*)&dm[w] = make_uint2(pack_bf16(o0 - trbf(o0), o1 - trbf(o1)),
                                     pack_bf16(o2 - trbf(o2), o3 - trbf(o3)));
        *(uint2*)&dr[w] = make_uint2(pack_bf16(o0, o1), pack_bf16(o2, o3));
    }
}

// ---------------------------------------------------------------------------
// Flash attention, TQ=128, 256 threads (R11 structure, both passes
// double-buffered). Pass A: 1-term rn-bf16 QK (unbiased; feeds only (m,s)).
// Pass B: full bf16x3 (bit-identical weights/out numerics to R11).
// ---------------------------------------------------------------------------
#define KSTR 36                       // words per K/V smem row (144 B)
#define STG  (128 * KSTR * 4)         // 18432 B per stage array
#define OFF_K0HI  0
#define OFF_K0MID (1 * STG)
#define OFF_K1HI  (2 * STG)
#define OFF_K1MID (3 * STG)
#define OFF_V0HI  (4 * STG)
#define OFF_V0MID (5 * STG)
#define OFF_V1HI  (6 * STG)
#define OFF_V1MID (7 * STG)
#define OFF_QHI   (8 * STG)
#define OFF_QMID  (9 * STG)
#define ATTN_SMEM (10 * STG)          // 184320 B

__device__ __forceinline__ void prefetch_kv(
    const uint32_t* __restrict__ KVh, const uint32_t* __restrict__ KVm,
    int rowbase, int voff, uint32_t dhi, uint32_t dmid, int tid)
{
#pragma unroll
    for (int i = 0; i < 8; i++) {
        int e = tid + i * 256;
        int r = e >> 4, t = e & 15, w8 = t & 7;
        const uint32_t* src = ((t & 8) ? KVm : KVh) + (size_t)(rowbase + r) * 64 + voff + w8 * 4;
        uint32_t dst = ((t & 8) ? dmid : dhi) + (uint32_t)(r * 144 + w8 * 16);
        CP_ASYNC16(dst, src);
    }
}

// single-array K prefetch for pass A (rn values, half the traffic)
__device__ __forceinline__ void prefetch_k_one(
    const uint32_t* __restrict__ src_arr, int rowbase, uint32_t dhi, int tid)
{
#pragma unroll
    for (int i = 0; i < 4; i++) {
        int e = tid + i * 256;
        int r = e >> 3, w8 = e & 7;
        CP_ASYNC16(dhi + (uint32_t)(r * 144 + w8 * 16),
                   src_arr + (size_t)(rowbase + r) * 64 + w8 * 4);
    }
}

__global__ __launch_bounds__(256, 1) void attn_flash(
    const uint32_t* __restrict__ Qh, const uint32_t* __restrict__ Qm,
    const uint32_t* __restrict__ Qr,
    const uint32_t* __restrict__ KVh, const uint32_t* __restrict__ KVm,
    const uint32_t* __restrict__ KVr,
    float* __restrict__ Wout, float* __restrict__ Aout)
{
    extern __shared__ char sm[];
    const int tid = threadIdx.x, wid = tid >> 5, lane = tid & 31;
    const int gid = lane >> 2, tig = lane & 3;
    const int b = blockIdx.z, h = blockIdx.y, q0 = blockIdx.x * 128;
    const uint32_t sb = smem_u32(sm);
    const int rb = b * SEQ;

    uint32_t* qw_hi  = (uint32_t*)(sm + OFF_QHI);
    uint32_t* qw_mid = (uint32_t*)(sm + OFF_QMID);
    uint32_t* qw_rn  = (uint32_t*)(sm + OFF_V0HI);   // scratch during pass A

    prefetch_k_one(KVr, rb, sb + OFF_K0HI, tid);
    CP_COMMIT();

    // stage Q rows q0..q0+127 (hi, mid, rn)
#pragma unroll
    for (int i = 0; i < 4; i++) {
        int e = tid + i * 256;
        int r = e >> 3, cw = (e & 7) * 4;
        size_t g = (size_t)(rb + q0 + r) * 512 + h * 32 + cw;
        *(uint4*)&qw_hi[r * KSTR + cw]  = *(const uint4*)&Qh[g];
        *(uint4*)&qw_mid[r * KSTR + cw] = *(const uint4*)&Qm[g];
        *(uint4*)&qw_rn[r * KSTR + cw]  = *(const uint4*)&Qr[g];
    }
    __syncthreads();

    // pass-A fragments: rn only (register-lean)
    uint32_t qr[4][4];
#pragma unroll
    for (int ds = 0; ds < 4; ds++) {
        int w0 = (wid * 16 + gid) * KSTR + ds * 8 + tig, w1 = w0 + 8 * KSTR;
        qr[ds][0] = qw_rn[w0];  qr[ds][1] = qw_rn[w1];
        qr[ds][2] = qw_rn[w0 + 4]; qr[ds][3] = qw_rn[w1 + 4];
    }

    float m0 = -1e30f, s0 = 0.f, m1 = -1e30f, s1 = 0.f;
    float c[16][4];

    // ---- Pass A: online row max & expsum (1-term rn QK) ----
    for (int ch = 0; ch < 16; ch++) {
        if (ch < 15) {
            int alt = (ch + 1) & 1;
            prefetch_k_one(KVr, rb + (ch + 1) * 128,
                           sb + (alt ? OFF_K1HI : OFF_K0HI), tid);
        }
        CP_COMMIT(); CP_WAIT1(); __syncthreads();
        const uint32_t* khi = (const uint32_t*)(sm + ((ch & 1) ? OFF_K1HI : OFF_K0HI));
#pragma unroll
        for (int j = 0; j < 16; j++) {
            c[j][0] = 0.f; c[j][1] = 0.f; c[j][2] = 0.f; c[j][3] = 0.f;
        }
#pragma unroll
        for (int ds = 0; ds < 4; ds++) {
#pragma unroll
            for (int j = 0; j < 16; j++) {
                int wi = (j * 8 + gid) * KSTR + ds * 8 + tig;
                uint32_t bh[2] = { khi[wi], khi[wi + 4] };
                mma_bf16(c[j], qr[ds], bh);
            }
        }
        float mx0 = -1e30f, mx1 = -1e30f;
#pragma unroll
        for (int j = 0; j < 16; j++) {
            mx0 = fmaxf(mx0, fmaxf(c[j][0], c[j][1]));
            mx1 = fmaxf(mx1, fmaxf(c[j][2], c[j][3]));
        }
        mx0 = fmaxf(mx0, __shfl_xor_sync(0xffffffffu, mx0, 1));
        mx0 = fmaxf(mx0, __shfl_xor_sync(0xffffffffu, mx0, 2));
        mx1 = fmaxf(mx1, __shfl_xor_sync(0xffffffffu, mx1, 1));
        mx1 = fmaxf(mx1, __shfl_xor_sync(0xffffffffu, mx1, 2));
        float nm0 = fmaxf(m0, mx0), nm1 = fmaxf(m1, mx1);
        float a0 = 0.f, a1 = 0.f;
#pragma unroll
        for (int j = 0; j < 16; j++) {
            a0 += __expf(c[j][0] - nm0) + __expf(c[j][1] - nm0);
            a1 += __expf(c[j][2] - nm1) + __expf(c[j][3] - nm1);
        }
        a0 += __shfl_xor_sync(0xffffffffu, a0, 1);
        a0 += __shfl_xor_sync(0xffffffffu, a0, 2);
        a1 += __shfl_xor_sync(0xffffffffu, a1, 1);
        a1 += __shfl_xor_sync(0xffffffffu, a1, 2);
        s0 = s0 * __expf(m0 - nm0) + a0; m0 = nm0;
        s1 = s1 * __expf(m1 - nm1) + a1; m1 = nm1;
        __syncthreads();
    }
    CP_WAIT0();
    const float inv0 = 1.f / s0, inv1 = 1.f / s1;
    __syncthreads();

    // pass-B fragments (Q smem still resident)
    uint32_t qh[4][4], qm[4][4];
#pragma unroll
    for (int ds = 0; ds < 4; ds++) {
        int w0 = (wid * 16 + gid) * KSTR + ds * 8 + tig, w1 = w0 + 8 * KSTR;
        qh[ds][0] = qw_hi[w0];  qh[ds][1] = qw_hi[w1];
        qh[ds][2] = qw_hi[w0 + 4]; qh[ds][3] = qw_hi[w1 + 4];
        qm[ds][0] = qw_mid[w0]; qm[ds][1] = qw_mid[w1];
        qm[ds][2] = qw_mid[w0 + 4]; qm[ds][3] = qw_mid[w1 + 4];
    }

    // ---- Pass B: weights + PV (full bf16x3, K+V double-buffered) ----
    prefetch_kv(KVh, KVm, rb, 0,  sb + OFF_K0HI, sb + OFF_K0MID, tid);
    prefetch_kv(KVh, KVm, rb, 32, sb + OFF_V0HI, sb + OFF_V0MID, tid);
    CP_COMMIT();

    float pv[8][4];
#pragma unroll
    for (int n = 0; n < 8; n++) { pv[n][0] = pv[n][1] = pv[n][2] = pv[n][3] = 0.f; }

    float* wrow0 = Wout + ((size_t)(b * NHEADS + h) * SEQ + (q0 + wid * 16 + gid)) * SEQ;
    float* wrow1 = wrow0 + (size_t)8 * SEQ;

    for (int ch = 0; ch < 16; ch++) {
        if (ch < 15) {
            int alt = (ch + 1) & 1;
            prefetch_kv(KVh, KVm, rb + (ch + 1) * 128, 0,
                        sb + (alt ? OFF_K1HI : OFF_K0HI),
                        sb + (alt ? OFF_K1MID : OFF_K0MID), tid);
            prefetch_kv(KVh, KVm, rb + (ch + 1) * 128, 32,
                        sb + (alt ? OFF_V1HI : OFF_V0HI),
                        sb + (alt ? OFF_V1MID : OFF_V0MID), tid);
        }
        CP_COMMIT(); CP_WAIT1(); __syncthreads();
        int cur = ch & 1;
        const uint32_t* khi  = (const uint32_t*)(sm + (cur ? OFF_K1HI : OFF_K0HI));
        const uint32_t* kmid = (const uint32_t*)(sm + (cur ? OFF_K1MID : OFF_K0MID));
        const uint32_t vbhi  = sb + (cur ? OFF_V1HI : OFF_V0HI);
        const uint32_t vbmid = sb + (cur ? OFF_V1MID : OFF_V0MID);

#pragma unroll
        for (int j = 0; j < 16; j++) {
            c[j][0] = 0.f; c[j][1] = 0.f; c[j][2] = 0.f; c[j][3] = 0.f;
        }
#pragma unroll
        for (int ds = 0; ds < 4; ds++) {
#pragma unroll
            for (int j = 0; j < 16; j++) {
                int wi = (j * 8 + gid) * KSTR + ds * 8 + tig;
                uint32_t bh[2] = { khi[wi],  khi[wi + 4]  };
                uint32_t bm[2] = { kmid[wi], kmid[wi + 4] };
                mma_bf16(c[j], qh[ds], bh);
                mma_bf16(c[j], qm[ds], bh);
                mma_bf16(c[j], qh[ds], bm);
            }
        }

#pragma unroll
        for (int j = 0; j < 16; j++) {
            float p0 = __expf(c[j][0] - m0) * inv0;
            float p1 = __expf(c[j][1] - m0) * inv0;
            float p2 = __expf(c[j][2] - m1) * inv1;
            float p3 = __expf(c[j][3] - m1) * inv1;
            *(float2*)&wrow0[ch * 128 + j * 8 + tig * 2] = make_float2(p0, p1);
            *(float2*)&wrow1[ch * 128 + j * 8 + tig * 2] = make_float2(p2, p3);
            c[j][0] = p0; c[j][1] = p1; c[j][2] = p2; c[j][3] = p3;
        }

#pragma unroll
        for (int s = 0; s < 8; s++) {
            uint32_t ah[4], am[4];
            float e00 = c[2*s][0],   e01 = c[2*s][1],   e02 = c[2*s][2],   e03 = c[2*s][3];
            float e10 = c[2*s+1][0], e11 = c[2*s+1][1], e12 = c[2*s+1][2], e13 = c[2*s+1][3];
            ah[0] = trunc_pack(e00, e01); ah[1] = trunc_pack(e02, e03);
            ah[2] = trunc_pack(e10, e11); ah[3] = trunc_pack(e12, e13);
            am[0] = pack_bf16(e00 - trbf(e00), e01 - trbf(e01));
            am[1] = pack_bf16(e02 - trbf(e02), e03 - trbf(e03));
            am[2] = pack_bf16(e10 - trbf(e10), e11 - trbf(e11));
            am[3] = pack_bf16(e12 - trbf(e12), e13 - trbf(e13));
            uint32_t vrow = (uint32_t)((s * 16 + (lane & 15)) * 144);
#pragma unroll
            for (int n = 0; n < 8; n++) {
                uint32_t bh[2], bm[2];
                LDSM_X2T(bh[0], bh[1], vbhi + vrow + n * 16);
                LDSM_X2T(bm[0], bm[1], vbmid + vrow + n * 16);
                mma_bf16(pv[n], ah, bh);
                mma_bf16(pv[n], am, bh);
                mma_bf16(pv[n], ah, bm);
            }
        }
        __syncthreads();
    }

    int row0 = rb + q0 + wid * 16 + gid;
#pragma unroll
    for (int n = 0; n < 8; n++) {
        int dcol = h * DEPTH + n * 8 + tig * 2;
        *(float2*)&Aout[(size_t)row0 * D_MODEL + dcol]       = make_float2(pv[n][0], pv[n][1]);
        *(float2*)&Aout[(size_t)(row0 + 8) * D_MODEL + dcol] = make_float2(pv[n][2], pv[n][3]);
    }
}

// ---------------------------------------------------------------------------
extern "C" void kernel_launch(void* const* d_in, const int* in_sizes, int n_in,
                              void* d_out, int out_size)
{
    const float* Q       = (const float*)d_in[0];
    const float* K       = (const float*)d_in[1];
    // d_in[2] = V (unused: reference derives V from the KV projection)
    const float* WQ_w    = (const float*)d_in[3];
    const float* WQ_b    = (const float*)d_in[4];
    const float* WKV_w   = (const float*)d_in[5];
    const float* WKV_b   = (const float*)d_in[6];
    const float* dense_w = (const float*)d_in[7];
    const float* dense_b = (const float*)d_in[8];

    float* out     = (float*)d_out;
    float* weights = out + (size_t)M_TOTAL * D_MODEL;

    float* attn;
    uint32_t *qhp, *qmp, *qrp, *kvh, *kvm, *kvr;
    cudaGetSymbolAddress((void**)&attn, g_attn);
    cudaGetSymbolAddress((void**)&qhp,  g_Qh);
    cudaGetSymbolAddress((void**)&qmp,  g_Qm);
    cudaGetSymbolAddress((void**)&qrp,  g_Qr);
    cudaGetSymbolAddress((void**)&kvh,  g_KVh);
    cudaGetSymbolAddress((void**)&kvm,  g_KVm);
    cudaGetSymbolAddress((void**)&kvr,  g_KVr);

    cudaFuncSetAttribute(attn_flash, cudaFuncAttributeMaxDynamicSharedMemorySize, ATTN_SMEM);

    // 1) Qp-split = 0.125*(Q @ WQ_w^T + b)  -> g_Qh/g_Qm/g_Qr
    gemm_tc<<<dim3(D_MODEL / 128, M_TOTAL / 128), 256>>>(
        Q, WQ_w, WQ_b, nullptr, qhp, qmp, qrp, 0.125f, M_TOTAL, D_MODEL, D_MODEL);
    // 2) KV-split = K @ WKV_w^T + b (exact fp32 compute) -> g_KVh/g_KVm/g_KVr
    gemm_kv_split<<<dim3((2 * DEPTH) / 64, M_TOTAL / 64), 256>>>(
        K, WKV_w, WKV_b, kvh, kvm, kvr, M_TOTAL, 2 * DEPTH, D_MODEL);
    // 3) flash attention: weights + context
    attn_flash<<<dim3(SEQ / 128, NHEADS, BATCH), 256, ATTN_SMEM>>>(
        qhp, qmp, qrp, kvh, kvm, kvr, weights, attn);
    // 4) out = attn @ dense_w^T + b (fp32 output)
    gemm_tc<<<dim3(D_MODEL / 128, M_TOTAL / 128), 256>>>(
        attn, dense_w, dense_b, out, nullptr, nullptr, nullptr, 1.f,
        M_TOTAL, D_MODEL, D_MODEL);
}